// round 13
// baseline (speedup 1.0000x reference)
#include <cuda_runtime.h>
#include <cuda_bf16.h>

// Problem constants
#define Bc  32
#define Nc  1024
#define Tc  64
#define Dc  32
#define NTc 1088   // N + T

#define NITEMS 6704
#define NCTAS  740   // 148 SMs x 5 resident CTAs: exactly one wave

__device__ float g_sa[Bc * Nc * Dc];
__device__ float g_tb[Bc * Nc * Dc];
__device__ float g_sb[Bc * Tc * Dc];
__device__ float g_ta[Bc * Tc * Dc];

// proj-done flag + consumer counter (reset by last consumer each launch)
__device__ int g_done = 0;
__device__ int g_consumed = 0;

__device__ __forceinline__ float tanh_ap(float x) {
    float y;
    asm("tanh.approx.f32 %0, %1;" : "=f"(y) : "f"(x));
    return y;
}
__device__ __forceinline__ float tanh_relu(float x) {
    return tanh_ap(fmaxf(x, 0.0f));
}

__device__ __forceinline__ unsigned tf32_hi(float x) {
    unsigned h;
    asm("cvt.rna.tf32.f32 %0, %1;" : "=r"(h) : "f"(x));
    return h;
}

__device__ __forceinline__ void mma_tf32(float* c, const unsigned* a,
                                         unsigned b0, unsigned b1) {
    asm("mma.sync.aligned.m16n8k8.row.col.f32.tf32.tf32.f32 "
        "{%0,%1,%2,%3}, {%4,%5,%6,%7}, {%8,%9}, {%0,%1,%2,%3};"
        : "+f"(c[0]), "+f"(c[1]), "+f"(c[2]), "+f"(c[3])
        : "r"(a[0]), "r"(a[1]), "r"(a[2]), "r"(a[3]), "r"(b0), "r"(b1));
}

// ---------------------------------------------------------------------------
// Persistent fused kernel: 740 CTAs loop over 6704 work items.
//   [0,272)        proj (4 row-tiles each) -> g_*, then signal g_done
//                  (first item of CTAs 0..271 -> done early, no deadlock)
//   [272,740)      gram
//   [740,6628)     period-23: 15 gram + 8 pair
//   [6628,6672)    gram tail (44)
//   [6672,6704)    gram BR (32)
// ---------------------------------------------------------------------------
__global__ void __launch_bounds__(256, 5)
fused_kernel(const float* __restrict__ sp, const float* __restrict__ tp,
             const float* __restrict__ st_w1, const float* __restrict__ st_b1,
             const float* __restrict__ st_w2, const float* __restrict__ st_b2,
             const float* __restrict__ ts_w1, const float* __restrict__ ts_b1,
             const float* __restrict__ ts_w2, const float* __restrict__ ts_b2,
             float* __restrict__ out)
{
    __shared__ __align__(16) float sbuf[4800];   // 19.2 KB
    int tid = threadIdx.x;

    for (int idx = blockIdx.x; idx < NITEMS; idx += NCTAS) {
        __syncthreads();   // smem reuse barrier between items

        int g = -1, p = -1;
        if (idx < 272) {
            // ------------------------ proj item ----------------------------
            float* xs = sbuf;            // [32][33]
            float* wa = sbuf + 1056;     // [32][32]
            float* wb = sbuf + 2080;     // [32][32]

            int tile0 = idx * 4;
            bool is_sp = tile0 < 1024;   // 1024 spatial tiles, 64 temporal

            for (int i = tid; i < 1024; i += 256) {
                int k = i >> 5, dd = i & 31;
                if (is_sp) {
                    wa[i] = st_w1[k * 32 + dd];
                    wb[i] = ts_w1[(32 + k) * 32 + dd];
                } else {
                    wa[i] = st_w1[(32 + k) * 32 + dd];
                    wb[i] = ts_w1[k * 32 + dd];
                }
            }

            int d  = tid & 31;
            int ty = tid >> 5;
            float b1a = is_sp ? 0.f : st_b1[d];
            float b1b = is_sp ? 0.f : ts_b1[d];

            float* o1 = is_sp ? g_sa : g_sb;
            float* o2 = is_sp ? g_tb : g_ta;

            for (int j = 0; j < 4; ++j) {
                int gr0 = (tile0 + j) * 32;
                const float* src = is_sp ? (sp + (size_t)gr0 * Dc)
                                         : (tp + (size_t)(gr0 - Bc * Nc) * Dc);
                __syncthreads();
                for (int i = tid; i < 1024; i += 256)
                    xs[(i >> 5) * 33 + (i & 31)] = src[i];
                __syncthreads();

                float acc1[4], acc2[4];
                #pragma unroll
                for (int rr = 0; rr < 4; ++rr) { acc1[rr] = b1a; acc2[rr] = b1b; }

                #pragma unroll 4
                for (int k = 0; k < 32; ++k) {
                    float wav = wa[k * 32 + d];
                    float wbv = wb[k * 32 + d];
                    #pragma unroll
                    for (int rr = 0; rr < 4; ++rr) {
                        float x = xs[(ty + 8 * rr) * 33 + k];
                        acc1[rr] = fmaf(x, wav, acc1[rr]);
                        acc2[rr] = fmaf(x, wbv, acc2[rr]);
                    }
                }

                size_t base = is_sp ? (size_t)gr0 : (size_t)(gr0 - Bc * Nc);
                #pragma unroll
                for (int rr = 0; rr < 4; ++rr) {
                    size_t rw = base + ty + 8 * rr;
                    o1[rw * 32 + d] = 0.5f * acc1[rr];
                    o2[rw * 32 + d] = 0.5f * acc2[rr];
                }
            }

            __syncthreads();
            if (tid == 0) {
                __threadfence();
                atomicAdd(&g_done, 1);
            }
            continue;
        } else if (idx < 740) {
            g = idx - 272;                       // 0..467
        } else if (idx < 6628) {
            int u = idx - 740, q = u / 23, r = u % 23;
            if (r < 15) g = 468 + q * 15 + r;    // 468..4307
            else        p = q * 8 + (r - 15);    // 0..2047
        } else if (idx < 6672) {
            g = 4308 + (idx - 6628);             // 4308..4351
        } else {
            // ------------------- gram BR: tanh(relu(T @ T^T)) ---------------
            int b = idx - 6672;
            float* ts_s = sbuf;   // [64][33]
            const float* tb = tp + (size_t)b * Tc * Dc;
            for (int i = tid; i < 2048; i += 256)
                ts_s[(i >> 5) * 33 + (i & 31)] = tb[i];
            __syncthreads();

            float* ob = out + (size_t)b * NTc * NTc;
            for (int it = 0; it < 16; ++it) {
                int e = tid + 256 * it;
                int i = e >> 6, j = e & 63;
                float acc = 0.f;
                #pragma unroll
                for (int k = 0; k < 32; ++k)
                    acc = fmaf(ts_s[i * 33 + k], ts_s[j * 33 + k], acc);
                ob[(size_t)(Nc + i) * NTc + (Nc + j)] = tanh_relu(acc);
            }
            continue;
        }

        if (g >= 0) {
            // ------ gram TL: tanh(relu(S @ S^T)), 64x64 tile, tf32 MMA ------
            int b = g / 136, t = g % 136;
            int R = 0, rem = t;
            while (rem >= 16 - R) { rem -= 16 - R; ++R; }
            int C = R + rem;
            int r0 = R * 64, c0 = C * 64;
            bool mirror = (C > R);

            unsigned* As = reinterpret_cast<unsigned*>(sbuf);          // [64][36] tf32
            unsigned* Bs = reinterpret_cast<unsigned*>(sbuf) + 2304;   // [64][36]
            unsigned* BsP = mirror ? Bs : As;

            const float* Xb = sp + (size_t)b * Nc * Dc;
            for (int i = tid; i < 512; i += 256) {
                int row = i >> 3, kq = i & 7;
                float4 v = *reinterpret_cast<const float4*>(
                    Xb + (size_t)(r0 + row) * 32 + kq * 4);
                uint4 tv;
                tv.x = tf32_hi(v.x); tv.y = tf32_hi(v.y);
                tv.z = tf32_hi(v.z); tv.w = tf32_hi(v.w);
                *reinterpret_cast<uint4*>(As + row * 36 + kq * 4) = tv;
            }
            if (mirror) {
                for (int i = tid; i < 512; i += 256) {
                    int row = i >> 3, kq = i & 7;
                    float4 v = *reinterpret_cast<const float4*>(
                        Xb + (size_t)(c0 + row) * 32 + kq * 4);
                    uint4 tv;
                    tv.x = tf32_hi(v.x); tv.y = tf32_hi(v.y);
                    tv.z = tf32_hi(v.z); tv.w = tf32_hi(v.w);
                    *reinterpret_cast<uint4*>(Bs + row * 36 + kq * 4) = tv;
                }
            }
            __syncthreads();

            int w    = tid >> 5, lane = tid & 31;
            int wr   = w & 3;           // row quarter: rows 16wr..16wr+15
            int wcol = w >> 2;          // col half: cols 32wcol..+31
            int gg   = lane >> 2;       // groupID 0..7
            int tig  = lane & 3;        // thread-in-group 0..3

            const unsigned* arow = As + (16 * wr + gg) * 36;

            float acc[4][4];
            #pragma unroll
            for (int nf = 0; nf < 4; ++nf)
                #pragma unroll
                for (int e = 0; e < 4; ++e) acc[nf][e] = 0.f;

            #pragma unroll
            for (int s = 0; s < 4; ++s) {
                int ks = 8 * s;
                unsigned ahi[4];
                ahi[0] = arow[ks + tig];
                ahi[1] = arow[8 * 36 + ks + tig];
                ahi[2] = arow[ks + tig + 4];
                ahi[3] = arow[8 * 36 + ks + tig + 4];

                #pragma unroll
                for (int nf = 0; nf < 4; ++nf) {
                    const unsigned* brow = BsP + (32 * wcol + 8 * nf + gg) * 36;
                    unsigned bh0 = brow[ks + tig];
                    unsigned bh1 = brow[ks + tig + 4];
                    mma_tf32(acc[nf], ahi, bh0, bh1);
                }
            }

            float* ob = out + (size_t)b * NTc * NTc;
            int rowA = r0 + 16 * wr + gg;
            #pragma unroll
            for (int nf = 0; nf < 4; ++nf) {
                #pragma unroll
                for (int e = 0; e < 4; ++e) acc[nf][e] = tanh_relu(acc[nf][e]);
                int col = c0 + 32 * wcol + 8 * nf + 2 * tig;
                float2 p0; p0.x = acc[nf][0]; p0.y = acc[nf][1];
                float2 p1; p1.x = acc[nf][2]; p1.y = acc[nf][3];
                *reinterpret_cast<float2*>(ob + (size_t)rowA * NTc + col) = p0;
                *reinterpret_cast<float2*>(ob + (size_t)(rowA + 8) * NTc + col) = p1;
            }

            if (mirror) {
                __syncthreads();          // all warps done reading As/Bs
                float* Ms = sbuf;         // [64][68]: Ms[col_local][row_local]
                int rl = 16 * wr + gg;
                #pragma unroll
                for (int nf = 0; nf < 4; ++nf) {
                    int cl = 32 * wcol + 8 * nf + 2 * tig;
                    Ms[(cl    ) * 68 + rl    ] = acc[nf][0];
                    Ms[(cl + 1) * 68 + rl    ] = acc[nf][1];
                    Ms[(cl    ) * 68 + rl + 8] = acc[nf][2];
                    Ms[(cl + 1) * 68 + rl + 8] = acc[nf][3];
                }
                __syncthreads();
                int c  = tid >> 2;        // 0..63 (mirror row = original col)
                int qd = tid & 3;
                #pragma unroll
                for (int u = 0; u < 4; ++u) {
                    float4 v = *reinterpret_cast<float4*>(Ms + c * 68 + qd * 16 + 4 * u);
                    *reinterpret_cast<float4*>(
                        ob + (size_t)(c0 + c) * NTc + r0 + qd * 16 + 4 * u) = v;
                }
            }
        } else {
            // --------- bilinear MLP pair item: 32x64 tile -------------------
            int RA, CB, ROFF, COFF, r0, c0, b;
            const float *Arow, *Bcol, *w2, *b2;
            if (p < 1024) {            // st: rows spatial, cols temporal
                b = p >> 5; r0 = (p & 31) * 32; c0 = 0;
                RA = Nc; CB = Tc; ROFF = 0; COFF = Nc;
                Arow = g_sa; Bcol = g_sb; w2 = st_w2; b2 = st_b2;
            } else {                   // ts: rows temporal, cols spatial
                int s2 = p - 1024;
                b = s2 >> 5;
                int sub = s2 & 31;
                r0 = (sub & 1) * 32; c0 = (sub >> 1) * 64;
                RA = Tc; CB = Nc; ROFF = Nc; COFF = 0;
                Arow = g_ta; Bcol = g_tb; w2 = ts_w2; b2 = ts_b2;
            }

            float* rs  = sbuf;          // [32][36] (v4-aligned rows)
            float* cs  = sbuf + 1152;   // [64][33] (CF scalar reads)
            float* w2s = sbuf + 3264;   // [32]
            float* wcp = sbuf + 3296;   // [1]

            // w2/b2 are kernel inputs — load before the wait.
            if (tid < 32) w2s[tid] = w2[tid];

            // Wait for proj completion (proj = first items of CTAs 0..271).
            if (tid == 0) {
                while (*((volatile int*)&g_done) < 272) { }
                __threadfence();
                int old = atomicAdd(&g_consumed, 1);
                if (old == 2047) {          // last passer resets for replay
                    g_done = 0;
                    g_consumed = 0;
                    __threadfence();
                }
            }
            __syncthreads();

            for (int i = tid; i < 1024; i += 256)
                rs[(i >> 5) * 36 + (i & 31)] =
                    Arow[((size_t)b * RA + r0 + (i >> 5)) * 32 + (i & 31)];
            for (int i = tid; i < 2048; i += 256)
                cs[(i >> 5) * 33 + (i & 31)] =
                    Bcol[((size_t)b * CB + c0 + (i >> 5)) * 32 + (i & 31)];
            __syncthreads();
            if (tid == 0) {
                float s = 0.f;
                #pragma unroll
                for (int d = 0; d < 32; ++d) s += w2s[d];
                wcp[0] = fmaf(0.5f, s, b2[0]);
            }
            __syncthreads();

            int tc = tid & 63;
            int tr = tid >> 6;

            const float4* w2v = reinterpret_cast<const float4*>(w2s);
            const float* crow = cs + tc * 33;

            float acc[8];
            #pragma unroll
            for (int ii = 0; ii < 8; ++ii) acc[ii] = 0.f;

            #pragma unroll
            for (int dq = 0; dq < 8; ++dq) {
                float4 wv = w2v[dq];
                float cv0 = crow[dq * 4 + 0];
                float cv1 = crow[dq * 4 + 1];
                float cv2 = crow[dq * 4 + 2];
                float cv3 = crow[dq * 4 + 3];
                #pragma unroll
                for (int ii = 0; ii < 8; ++ii) {
                    float4 rv = *reinterpret_cast<const float4*>(
                        rs + (tr + 4 * ii) * 36 + dq * 4);
                    float s;
                    s  = wv.x * tanh_ap(rv.x + cv0);
                    s  = fmaf(wv.y, tanh_ap(rv.y + cv1), s);
                    s  = fmaf(wv.z, tanh_ap(rv.z + cv2), s);
                    s  = fmaf(wv.w, tanh_ap(rv.w + cv3), s);
                    acc[ii] += s;
                }
            }

            float wconst = wcp[0];
            float* ob = out + (size_t)b * NTc * NTc;
            #pragma unroll
            for (int ii = 0; ii < 8; ++ii)
                ob[(size_t)(ROFF + r0 + tr + 4 * ii) * NTc + (COFF + c0 + tc)]
                    = tanh_relu(fmaf(0.5f, acc[ii], wconst));
        }
    }
}

// ---------------------------------------------------------------------------
extern "C" void kernel_launch(void* const* d_in, const int* in_sizes, int n_in,
                              void* d_out, int out_size)
{
    const float* sp    = (const float*)d_in[0];
    const float* tp    = (const float*)d_in[1];
    const float* st_w1 = (const float*)d_in[2];
    const float* st_b1 = (const float*)d_in[3];
    const float* st_w2 = (const float*)d_in[4];
    const float* st_b2 = (const float*)d_in[5];
    const float* ts_w1 = (const float*)d_in[6];
    const float* ts_b1 = (const float*)d_in[7];
    const float* ts_w2 = (const float*)d_in[8];
    const float* ts_b2 = (const float*)d_in[9];
    float* out = (float*)d_out;

    fused_kernel<<<NCTAS, 256>>>(sp, tp, st_w1, st_b1, st_w2, st_b2,
                                 ts_w1, ts_b1, ts_w2, ts_b2, out);
}

// round 14
// speedup vs baseline: 1.1279x; 1.1279x over previous
#include <cuda_runtime.h>
#include <cuda_bf16.h>
#include <cuda_fp16.h>

// Problem constants
#define Bc  32
#define Nc  1024
#define Tc  64
#define Dc  32
#define NTc 1088   // N + T

__device__ float g_sa[Bc * Nc * Dc];
__device__ float g_tb[Bc * Nc * Dc];
__device__ float g_sb[Bc * Tc * Dc];
__device__ float g_ta[Bc * Tc * Dc];

// proj-done flag + consumer counter (reset by last consumer each launch)
__device__ int g_done = 0;
__device__ int g_consumed = 0;

__device__ __forceinline__ float tanh_ap(float x) {
    float y;
    asm("tanh.approx.f32 %0, %1;" : "=f"(y) : "f"(x));
    return y;
}
__device__ __forceinline__ float tanh_relu(float x) {
    return tanh_ap(fmaxf(x, 0.0f));
}
__device__ __forceinline__ __half2 tanh2_ap(__half2 x) {
    unsigned xi = *reinterpret_cast<unsigned*>(&x);
    unsigned yi;
    asm("tanh.approx.f16x2 %0, %1;" : "=r"(yi) : "r"(xi));
    return *reinterpret_cast<__half2*>(&yi);
}

__device__ __forceinline__ unsigned tf32_hi(float x) {
    unsigned h;
    asm("cvt.rna.tf32.f32 %0, %1;" : "=r"(h) : "f"(x));
    return h;
}

__device__ __forceinline__ void mma_tf32(float* c, const unsigned* a,
                                         unsigned b0, unsigned b1) {
    asm("mma.sync.aligned.m16n8k8.row.col.f32.tf32.tf32.f32 "
        "{%0,%1,%2,%3}, {%4,%5,%6,%7}, {%8,%9}, {%0,%1,%2,%3};"
        : "+f"(c[0]), "+f"(c[1]), "+f"(c[2]), "+f"(c[3])
        : "r"(a[0]), "r"(a[1]), "r"(a[2]), "r"(a[3]), "r"(b0), "r"(b1));
}

// ---------------------------------------------------------------------------
// Single fused kernel, 6704 blocks (R12 layout):
//   [0,272)        proj (4 row-tiles each) -> g_*, then signal g_done
//   [272,740)      gram (wave-1 filler; no dependency)
//   [740,6628)     period-23: 15 gram + 8 pair
//   [6628,6672)    gram tail (44)
//   [6672,6704)    gram BR (32)
// Pair path computes the 32-term tanh sum in half2 (tanh.approx.f16x2),
// two half2 accumulators per output, fp32 reduce + output activation.
// ---------------------------------------------------------------------------
__global__ void __launch_bounds__(256, 5)
fused_kernel(const float* __restrict__ sp, const float* __restrict__ tp,
             const float* __restrict__ st_w1, const float* __restrict__ st_b1,
             const float* __restrict__ st_w2, const float* __restrict__ st_b2,
             const float* __restrict__ ts_w1, const float* __restrict__ ts_b1,
             const float* __restrict__ ts_w2, const float* __restrict__ ts_b2,
             float* __restrict__ out)
{
    __shared__ __align__(16) float sbuf[4800];   // 19.2 KB
    int idx = blockIdx.x;
    int tid = threadIdx.x;

    int g = -1, p = -1;
    if (idx < 272) {
        // ------------------------ proj blocks ------------------------------
        float* xs = sbuf;            // [32][33]
        float* wa = sbuf + 1056;     // [32][32]
        float* wb = sbuf + 2080;     // [32][32]

        int tile0 = idx * 4;
        bool is_sp = tile0 < 1024;   // 1024 spatial tiles, 64 temporal

        for (int i = tid; i < 1024; i += 256) {
            int k = i >> 5, dd = i & 31;
            if (is_sp) {
                wa[i] = st_w1[k * 32 + dd];
                wb[i] = ts_w1[(32 + k) * 32 + dd];
            } else {
                wa[i] = st_w1[(32 + k) * 32 + dd];
                wb[i] = ts_w1[k * 32 + dd];
            }
        }

        int d  = tid & 31;
        int ty = tid >> 5;
        float b1a = is_sp ? 0.f : st_b1[d];
        float b1b = is_sp ? 0.f : ts_b1[d];

        float* o1 = is_sp ? g_sa : g_sb;
        float* o2 = is_sp ? g_tb : g_ta;

        for (int j = 0; j < 4; ++j) {
            int gr0 = (tile0 + j) * 32;
            const float* src = is_sp ? (sp + (size_t)gr0 * Dc)
                                     : (tp + (size_t)(gr0 - Bc * Nc) * Dc);
            __syncthreads();
            for (int i = tid; i < 1024; i += 256)
                xs[(i >> 5) * 33 + (i & 31)] = src[i];
            __syncthreads();

            float acc1[4], acc2[4];
            #pragma unroll
            for (int rr = 0; rr < 4; ++rr) { acc1[rr] = b1a; acc2[rr] = b1b; }

            #pragma unroll 4
            for (int k = 0; k < 32; ++k) {
                float wav = wa[k * 32 + d];
                float wbv = wb[k * 32 + d];
                #pragma unroll
                for (int rr = 0; rr < 4; ++rr) {
                    float x = xs[(ty + 8 * rr) * 33 + k];
                    acc1[rr] = fmaf(x, wav, acc1[rr]);
                    acc2[rr] = fmaf(x, wbv, acc2[rr]);
                }
            }

            size_t base = is_sp ? (size_t)gr0 : (size_t)(gr0 - Bc * Nc);
            #pragma unroll
            for (int rr = 0; rr < 4; ++rr) {
                size_t rw = base + ty + 8 * rr;
                o1[rw * 32 + d] = 0.5f * acc1[rr];
                o2[rw * 32 + d] = 0.5f * acc2[rr];
            }
        }

        __syncthreads();
        if (tid == 0) {
            __threadfence();
            atomicAdd(&g_done, 1);
        }
        return;
    } else if (idx < 740) {
        g = idx - 272;                       // 0..467
    } else if (idx < 6628) {
        int u = idx - 740, q = u / 23, r = u % 23;
        if (r < 15) g = 468 + q * 15 + r;    // 468..4307
        else        p = q * 8 + (r - 15);    // 0..2047
    } else if (idx < 6672) {
        g = 4308 + (idx - 6628);             // 4308..4351
    } else {
        // ------------------- gram BR: tanh(relu(T @ T^T)) -------------------
        int b = idx - 6672;
        float* ts_s = sbuf;   // [64][33]
        const float* tb = tp + (size_t)b * Tc * Dc;
        for (int i = tid; i < 2048; i += 256)
            ts_s[(i >> 5) * 33 + (i & 31)] = tb[i];
        __syncthreads();

        float* ob = out + (size_t)b * NTc * NTc;
        for (int it = 0; it < 16; ++it) {
            int e = tid + 256 * it;
            int i = e >> 6, j = e & 63;
            float acc = 0.f;
            #pragma unroll
            for (int k = 0; k < 32; ++k)
                acc = fmaf(ts_s[i * 33 + k], ts_s[j * 33 + k], acc);
            ob[(size_t)(Nc + i) * NTc + (Nc + j)] = tanh_relu(acc);
        }
        return;
    }

    if (g >= 0) {
        // -------- gram TL: tanh(relu(S @ S^T)), 64x64 tile, tf32 MMA --------
        int b = g / 136, t = g % 136;
        int R = 0, rem = t;
        while (rem >= 16 - R) { rem -= 16 - R; ++R; }
        int C = R + rem;
        int r0 = R * 64, c0 = C * 64;
        bool mirror = (C > R);

        unsigned* As = reinterpret_cast<unsigned*>(sbuf);          // [64][36] tf32
        unsigned* Bs = reinterpret_cast<unsigned*>(sbuf) + 2304;   // [64][36]
        unsigned* BsP = mirror ? Bs : As;

        const float* Xb = sp + (size_t)b * Nc * Dc;
        for (int i = tid; i < 512; i += 256) {
            int row = i >> 3, kq = i & 7;
            float4 v = *reinterpret_cast<const float4*>(
                Xb + (size_t)(r0 + row) * 32 + kq * 4);
            uint4 tv;
            tv.x = tf32_hi(v.x); tv.y = tf32_hi(v.y);
            tv.z = tf32_hi(v.z); tv.w = tf32_hi(v.w);
            *reinterpret_cast<uint4*>(As + row * 36 + kq * 4) = tv;
        }
        if (mirror) {
            for (int i = tid; i < 512; i += 256) {
                int row = i >> 3, kq = i & 7;
                float4 v = *reinterpret_cast<const float4*>(
                    Xb + (size_t)(c0 + row) * 32 + kq * 4);
                uint4 tv;
                tv.x = tf32_hi(v.x); tv.y = tf32_hi(v.y);
                tv.z = tf32_hi(v.z); tv.w = tf32_hi(v.w);
                *reinterpret_cast<uint4*>(Bs + row * 36 + kq * 4) = tv;
            }
        }
        __syncthreads();

        int w    = tid >> 5, lane = tid & 31;
        int wr   = w & 3;           // row quarter: rows 16wr..16wr+15
        int wcol = w >> 2;          // col half: cols 32wcol..+31
        int gg   = lane >> 2;       // groupID 0..7
        int tig  = lane & 3;        // thread-in-group 0..3

        const unsigned* arow = As + (16 * wr + gg) * 36;

        float acc[4][4];
        #pragma unroll
        for (int nf = 0; nf < 4; ++nf)
            #pragma unroll
            for (int e = 0; e < 4; ++e) acc[nf][e] = 0.f;

        #pragma unroll
        for (int s = 0; s < 4; ++s) {
            int ks = 8 * s;
            unsigned ahi[4];
            ahi[0] = arow[ks + tig];
            ahi[1] = arow[8 * 36 + ks + tig];
            ahi[2] = arow[ks + tig + 4];
            ahi[3] = arow[8 * 36 + ks + tig + 4];

            #pragma unroll
            for (int nf = 0; nf < 4; ++nf) {
                const unsigned* brow = BsP + (32 * wcol + 8 * nf + gg) * 36;
                unsigned bh0 = brow[ks + tig];
                unsigned bh1 = brow[ks + tig + 4];
                mma_tf32(acc[nf], ahi, bh0, bh1);
            }
        }

        float* ob = out + (size_t)b * NTc * NTc;
        int rowA = r0 + 16 * wr + gg;
        #pragma unroll
        for (int nf = 0; nf < 4; ++nf) {
            #pragma unroll
            for (int e = 0; e < 4; ++e) acc[nf][e] = tanh_relu(acc[nf][e]);
            int col = c0 + 32 * wcol + 8 * nf + 2 * tig;
            float2 p0; p0.x = acc[nf][0]; p0.y = acc[nf][1];
            float2 p1; p1.x = acc[nf][2]; p1.y = acc[nf][3];
            *reinterpret_cast<float2*>(ob + (size_t)rowA * NTc + col) = p0;
            *reinterpret_cast<float2*>(ob + (size_t)(rowA + 8) * NTc + col) = p1;
        }

        if (mirror) {
            __syncthreads();          // all warps done reading As/Bs
            float* Ms = sbuf;         // [64][68]: Ms[col_local][row_local]
            int rl = 16 * wr + gg;
            #pragma unroll
            for (int nf = 0; nf < 4; ++nf) {
                int cl = 32 * wcol + 8 * nf + 2 * tig;
                Ms[(cl    ) * 68 + rl    ] = acc[nf][0];
                Ms[(cl + 1) * 68 + rl    ] = acc[nf][1];
                Ms[(cl    ) * 68 + rl + 8] = acc[nf][2];
                Ms[(cl + 1) * 68 + rl + 8] = acc[nf][3];
            }
            __syncthreads();
            int c  = tid >> 2;        // 0..63 (mirror row = original col)
            int qd = tid & 3;
            #pragma unroll
            for (int u = 0; u < 4; ++u) {
                float4 v = *reinterpret_cast<float4*>(Ms + c * 68 + qd * 16 + 4 * u);
                *reinterpret_cast<float4*>(
                    ob + (size_t)(c0 + c) * NTc + r0 + qd * 16 + 4 * u) = v;
            }
        }
    } else {
        // ----------- bilinear MLP pair blocks: 32x64 tile, half2 math -------
        int RA, CB, ROFF, COFF, r0, c0, b;
        const float *Arow, *Bcol, *w2, *b2;
        if (p < 1024) {            // st: rows spatial, cols temporal
            b = p >> 5; r0 = (p & 31) * 32; c0 = 0;
            RA = Nc; CB = Tc; ROFF = 0; COFF = Nc;
            Arow = g_sa; Bcol = g_sb; w2 = st_w2; b2 = st_b2;
        } else {                   // ts: rows temporal, cols spatial
            int s2 = p - 1024;
            b = s2 >> 5;
            int sub = s2 & 31;
            r0 = (sub & 1) * 32; c0 = (sub >> 1) * 64;
            RA = Tc; CB = Nc; ROFF = Nc; COFF = 0;
            Arow = g_ta; Bcol = g_tb; w2 = ts_w2; b2 = ts_b2;
        }

        __half2* rsh = reinterpret_cast<__half2*>(sbuf);          // [32][18]
        __half2* csh = reinterpret_cast<__half2*>(sbuf) + 576;    // [64][17]
        float*   w2s = sbuf + 1664;                               // [32]
        __half2* w2h = reinterpret_cast<__half2*>(sbuf + 1696);   // [16]
        float*   wcp = sbuf + 1712;                               // [1]

        // w2/b2 are kernel inputs — load before the wait.
        if (tid < 32) w2s[tid] = w2[tid];

        // Wait for proj completion.
        if (tid == 0) {
            while (*((volatile int*)&g_done) < 272) { }
            __threadfence();
            int old = atomicAdd(&g_consumed, 1);
            if (old == 2047) {          // last passer resets for replay
                g_done = 0;
                g_consumed = 0;
                __threadfence();
            }
        }
        __syncthreads();

        // Fill in half2 (d-pairs).
        for (int i = tid; i < 512; i += 256) {       // rs: 32 rows x 16 h
            int row = i >> 4, h = i & 15;
            float2 v = *reinterpret_cast<const float2*>(
                Arow + ((size_t)b * RA + r0 + row) * 32 + h * 2);
            rsh[row * 18 + h] = __floats2half2_rn(v.x, v.y);
        }
        for (int i = tid; i < 1024; i += 256) {      // cs: 64 rows x 16 h
            int row = i >> 4, h = i & 15;
            float2 v = *reinterpret_cast<const float2*>(
                Bcol + ((size_t)b * CB + c0 + row) * 32 + h * 2);
            csh[row * 17 + h] = __floats2half2_rn(v.x, v.y);
        }
        __syncthreads();
        if (tid < 16)
            w2h[tid] = __floats2half2_rn(w2s[2 * tid], w2s[2 * tid + 1]);
        if (tid == 0) {
            float s = 0.f;
            #pragma unroll
            for (int d = 0; d < 32; ++d) s += w2s[d];
            wcp[0] = fmaf(0.5f, s, b2[0]);
        }
        __syncthreads();

        int tc = tid & 63;
        int tr = tid >> 6;

        const __half2* crow = csh + tc * 17;   // bank = (17tc+h) mod 32: CF

        __half2 zero = __floats2half2_rn(0.f, 0.f);
        __half2 acc0[8], acc1[8];
        #pragma unroll
        for (int ii = 0; ii < 8; ++ii) { acc0[ii] = zero; acc1[ii] = zero; }

        #pragma unroll
        for (int h = 0; h < 16; ++h) {
            __half2 cv = crow[h];
            __half2 wv = w2h[h];
            #pragma unroll
            for (int ii = 0; ii < 8; ++ii) {
                __half2 rv = rsh[(tr + 4 * ii) * 18 + h];   // broadcast
                __half2 t  = tanh2_ap(__hadd2(rv, cv));
                if (h < 8) acc0[ii] = __hfma2(wv, t, acc0[ii]);
                else       acc1[ii] = __hfma2(wv, t, acc1[ii]);
            }
        }

        float wconst = wcp[0];
        float* ob = out + (size_t)b * NTc * NTc;
        #pragma unroll
        for (int ii = 0; ii < 8; ++ii) {
            float2 a0 = __half22float2(acc0[ii]);
            float2 a1 = __half22float2(acc1[ii]);
            float accf = (a0.x + a0.y) + (a1.x + a1.y);
            ob[(size_t)(ROFF + r0 + tr + 4 * ii) * NTc + (COFF + c0 + tc)]
                = tanh_relu(fmaf(0.5f, accf, wconst));
        }
    }
}

// ---------------------------------------------------------------------------
extern "C" void kernel_launch(void* const* d_in, const int* in_sizes, int n_in,
                              void* d_out, int out_size)
{
    const float* sp    = (const float*)d_in[0];
    const float* tp    = (const float*)d_in[1];
    const float* st_w1 = (const float*)d_in[2];
    const float* st_b1 = (const float*)d_in[3];
    const float* st_w2 = (const float*)d_in[4];
    const float* st_b2 = (const float*)d_in[5];
    const float* ts_w1 = (const float*)d_in[6];
    const float* ts_b1 = (const float*)d_in[7];
    const float* ts_w2 = (const float*)d_in[8];
    const float* ts_b2 = (const float*)d_in[9];
    float* out = (float*)d_out;

    fused_kernel<<<6704, 256>>>(sp, tp, st_w1, st_b1, st_w2, st_b2,
                                ts_w1, ts_b1, ts_w2, ts_b2, out);
}